// round 13
// baseline (speedup 1.0000x reference)
#include <cuda_runtime.h>
#include <cstdint>

// Problem constants
#define BB 256
#define NT 196
#define CC 784
#define HH 4
#define DD 196
#define MM (BB*NT)      // 50176
#define BH (BB*HH)      // 1024
#define KP 832          // 784 padded to 13*64

// ---------------------------------------------------------------------------
// Scratch (static __device__ — no allocations allowed).
// ---------------------------------------------------------------------------
__device__ float g_q[(size_t)BH*NT*DD];   // (b,h,n,d)
__device__ float g_k[(size_t)BH*NT*DD];
__device__ float g_v[(size_t)BH*NT*DD];
__device__ float g_s[(size_t)BH*NT*NT];   // scores -> attn (in place)
__device__ float g_o[(size_t)BB*NT*CC];   // (b,n,h*d)
__device__ float g_cp[(size_t)HH*NT*DD];  // cp[h][p][k]

// int8 split planes + scales
__device__ char  g_xh[(size_t)MM*KP],  g_xl[(size_t)MM*KP];
__device__ char  g_oh[(size_t)MM*KP],  g_ol[(size_t)MM*KP];
__device__ char  g_wh[(size_t)4*784*KP], g_wl[(size_t)4*784*KP];
__device__ float g_sx[MM], g_so[MM], g_sw[4*784];

// ---------------------------------------------------------------------------
// bf16 split helpers (attention path)
// ---------------------------------------------------------------------------
__device__ __forceinline__ void splitpair(float x, float y,
                                          uint32_t& hi, uint32_t& lo) {
    uint32_t h;
    asm("cvt.rn.bf16x2.f32 %0, %1, %2;" : "=r"(h) : "f"(y), "f"(x));
    float hx = __uint_as_float(h << 16);
    float hy = __uint_as_float(h & 0xffff0000u);
    asm("cvt.rn.bf16x2.f32 %0, %1, %2;" : "=r"(lo) : "f"(y - hy), "f"(x - hx));
    hi = h;
}
__device__ __forceinline__ void split4p(float4 v, uint2& hi, uint2& lo) {
    splitpair(v.x, v.y, hi.x, lo.x);
    splitpair(v.z, v.w, hi.y, lo.y);
}
__device__ __forceinline__ void mmabf(float* c, const uint32_t* a,
                                      uint32_t b0, uint32_t b1) {
    asm volatile("mma.sync.aligned.m16n8k16.row.col.f32.bf16.bf16.f32 "
                 "{%0,%1,%2,%3}, {%4,%5,%6,%7}, {%8,%9}, {%0,%1,%2,%3};"
                 : "+f"(c[0]), "+f"(c[1]), "+f"(c[2]), "+f"(c[3])
                 : "r"(a[0]), "r"(a[1]), "r"(a[2]), "r"(a[3]),
                   "r"(b0), "r"(b1));
}
__device__ __forceinline__ void imma32(int* c, const uint32_t* a,
                                       uint32_t b0, uint32_t b1) {
    asm volatile("mma.sync.aligned.m16n8k32.row.col.s32.s8.s8.s32 "
                 "{%0,%1,%2,%3}, {%4,%5,%6,%7}, {%8,%9}, {%0,%1,%2,%3};"
                 : "+r"(c[0]), "+r"(c[1]), "+r"(c[2]), "+r"(c[3])
                 : "r"(a[0]), "r"(a[1]), "r"(a[2]), "r"(a[3]),
                   "r"(b0), "r"(b1));
}

// ---------------------------------------------------------------------------
// cp[h][p][k] = rel_h[h][k][p/14] + rel_w[h][k][p%14]
// ---------------------------------------------------------------------------
__global__ void cp_kernel(const float* __restrict__ rel_h,
                          const float* __restrict__ rel_w) {
    int idx = blockIdx.x * blockDim.x + threadIdx.x;
    if (idx >= HH * NT * DD) return;
    int k = idx % DD;
    int p = (idx / DD) % NT;
    int h = idx / (DD * NT);
    g_cp[idx] = rel_h[(h * DD + k) * 14 + p / 14]
              + rel_w[(h * DD + k) * 14 + p % 14];
}

// ---------------------------------------------------------------------------
// Row quantizer: per-row absmax scale, 2-term int8 split, zero-padded to 832.
// sel: 0 = x -> g_xh/xl/sx; 1..4 = W(sel-1) -> g_wh/wl/sw plane; 5 = g_o.
// ---------------------------------------------------------------------------
__global__ __launch_bounds__(256)
void quant_rows(const float* __restrict__ Ain, int sel) {
    const float* A; char* H; char* L; float* RS;
    if (sel == 0)      { A = Ain;  H = g_xh; L = g_xl; RS = g_sx; }
    else if (sel <= 4) { A = Ain;
                         H = g_wh + (size_t)(sel - 1) * 784 * KP;
                         L = g_wl + (size_t)(sel - 1) * 784 * KP;
                         RS = g_sw + (sel - 1) * 784; }
    else               { A = g_o;  H = g_oh; L = g_ol; RS = g_so; }

    const int row = blockIdx.x;
    const int tid = threadIdx.x;
    const float* a = A + (size_t)row * 784;

    __shared__ float red[8];
    float mx = 0.f;
    for (int j = tid; j < 784; j += 256) mx = fmaxf(mx, fabsf(a[j]));
#pragma unroll
    for (int o = 16; o; o >>= 1)
        mx = fmaxf(mx, __shfl_xor_sync(0xffffffffu, mx, o));
    if ((tid & 31) == 0) red[tid >> 5] = mx;
    __syncthreads();
    if (tid == 0) {
        float m = red[0];
#pragma unroll
        for (int i = 1; i < 8; ++i) m = fmaxf(m, red[i]);
        red[0] = m;
        RS[row] = (m > 0.f) ? m / 127.f : 0.f;
    }
    __syncthreads();
    mx = red[0];
    float s = (mx > 0.f) ? 127.f / mx : 0.f;

    for (int j = tid; j < KP; j += 256) {
        float v = (j < 784) ? a[j] * s : 0.f;
        int h = __float2int_rn(v);
        int l = __float2int_rn((v - (float)h) * 128.f);
        H[(size_t)row * KP + j] = (char)h;
        L[(size_t)row * KP + j] = (char)l;
    }
}

// ---------------------------------------------------------------------------
// int8 projection GEMM: out = A(M x 784) @ W(784 x 784)^T + bias
// Block 128x112, BK=64, 256 threads (8 warps 4x2), warp tile 32x56,
// double-buffered smem, two s32 accumulators (hh, cross), fp32 descale.
// MODE 0: A = x planes, z = blockIdx.z in {q,k,v}, head-split scatter.
// MODE 1: A = g_o planes, W = Wo, plain store to d_out.
// ---------------------------------------------------------------------------
// dynamic smem layout (bytes): Ah[2][128*80] Al[2][...] Bh[2][112*80] Bl[2]
#define SA_H 0
#define SA_L 20480
#define SB_H 40960
#define SB_L 58880
#define SMEM_I8 76800

template <int MODE>
__global__ __launch_bounds__(256, 1)
void proj_i8(const float* __restrict__ b0p, const float* __restrict__ b1p,
             const float* __restrict__ b2p, float* __restrict__ outp) {
    extern __shared__ char sm[];
    const int tid = threadIdx.x;
    const int z = (MODE == 0) ? blockIdx.z : 3;
    const char* AH = (MODE == 0) ? g_xh : g_oh;
    const char* AL = (MODE == 0) ? g_xl : g_ol;
    const char* WH = g_wh + (size_t)z * 784 * KP;
    const char* WL = g_wl + (size_t)z * 784 * KP;
    const float* rsA = (MODE == 0) ? g_sx : g_so;
    const float* rsB = g_sw + z * 784;
    const float* bias = (MODE == 0) ? ((z == 0) ? b0p : (z == 1) ? b1p : b2p)
                                    : b0p;
    float* dst = (MODE == 0) ? ((z == 0) ? g_q : (z == 1) ? g_k : g_v) : outp;

    const int m0 = blockIdx.x * 128, n0 = blockIdx.y * 112;
    const int w = tid >> 5, lane = tid & 31;
    const int wm = (w >> 1) * 32, wn = (w & 1) * 56;
    const int g = lane >> 2, t = lane & 3;

    // gmem->smem mapping: unit i = (row = i>>2, seg16 = i&3)
    const int rA0 = tid >> 2, rA1 = (tid + 256) >> 2;
    const int sg = (tid & 3) * 16;
    const bool hasB1 = (tid + 256) < 448;
    const int rB1 = (tid + 256) >> 2;

    int acch[2][7][4], accc[2][7][4];
#pragma unroll
    for (int i = 0; i < 2; i++)
#pragma unroll
        for (int j = 0; j < 7; j++)
#pragma unroll
            for (int c = 0; c < 4; c++) { acch[i][j][c] = 0; accc[i][j][c] = 0; }

    // prologue: chunk 0 -> buf 0
    {
        *(uint4*)(sm + SA_H + rA0 * 80 + sg) =
            *(const uint4*)(AH + (size_t)(m0 + rA0) * KP + sg);
        *(uint4*)(sm + SA_H + rA1 * 80 + sg) =
            *(const uint4*)(AH + (size_t)(m0 + rA1) * KP + sg);
        *(uint4*)(sm + SA_L + rA0 * 80 + sg) =
            *(const uint4*)(AL + (size_t)(m0 + rA0) * KP + sg);
        *(uint4*)(sm + SA_L + rA1 * 80 + sg) =
            *(const uint4*)(AL + (size_t)(m0 + rA1) * KP + sg);
        *(uint4*)(sm + SB_H + rA0 * 80 + sg) =
            *(const uint4*)(WH + (size_t)(n0 + rA0) * KP + sg);
        *(uint4*)(sm + SB_L + rA0 * 80 + sg) =
            *(const uint4*)(WL + (size_t)(n0 + rA0) * KP + sg);
        if (hasB1) {
            *(uint4*)(sm + SB_H + rB1 * 80 + sg) =
                *(const uint4*)(WH + (size_t)(n0 + rB1) * KP + sg);
            *(uint4*)(sm + SB_L + rB1 * 80 + sg) =
                *(const uint4*)(WL + (size_t)(n0 + rB1) * KP + sg);
        }
    }
    __syncthreads();

    for (int ch = 0; ch < 13; ++ch) {
        const int bf = ch & 1;
        uint4 pah0, pah1, pal0, pal1, pbh0, pbl0, pbh1, pbl1;
        if (ch < 12) {
            int k0 = (ch + 1) * 64;
            pah0 = *(const uint4*)(AH + (size_t)(m0 + rA0) * KP + k0 + sg);
            pah1 = *(const uint4*)(AH + (size_t)(m0 + rA1) * KP + k0 + sg);
            pal0 = *(const uint4*)(AL + (size_t)(m0 + rA0) * KP + k0 + sg);
            pal1 = *(const uint4*)(AL + (size_t)(m0 + rA1) * KP + k0 + sg);
            pbh0 = *(const uint4*)(WH + (size_t)(n0 + rA0) * KP + k0 + sg);
            pbl0 = *(const uint4*)(WL + (size_t)(n0 + rA0) * KP + k0 + sg);
            if (hasB1) {
                pbh1 = *(const uint4*)(WH + (size_t)(n0 + rB1) * KP + k0 + sg);
                pbl1 = *(const uint4*)(WL + (size_t)(n0 + rB1) * KP + k0 + sg);
            }
        }

        // ---- compute on buf bf ----
        {
            const char* pAH = sm + SA_H + bf * 10240;
            const char* pAL = sm + SA_L + bf * 10240;
            const char* pBH = sm + SB_H + bf * 8960;
            const char* pBL = sm + SB_L + bf * 8960;
#pragma unroll
            for (int ks = 0; ks < 2; ++ks) {
                uint32_t ah[2][4], al[2][4];
#pragma unroll
                for (int mt = 0; mt < 2; ++mt) {
                    int r0 = (wm + mt * 16 + g) * 80 + ks * 32 + t * 4;
                    int r1 = (wm + mt * 16 + g + 8) * 80 + ks * 32 + t * 4;
                    ah[mt][0] = *(const uint32_t*)(pAH + r0);
                    ah[mt][1] = *(const uint32_t*)(pAH + r1);
                    ah[mt][2] = *(const uint32_t*)(pAH + r0 + 16);
                    ah[mt][3] = *(const uint32_t*)(pAH + r1 + 16);
                    al[mt][0] = *(const uint32_t*)(pAL + r0);
                    al[mt][1] = *(const uint32_t*)(pAL + r1);
                    al[mt][2] = *(const uint32_t*)(pAL + r0 + 16);
                    al[mt][3] = *(const uint32_t*)(pAL + r1 + 16);
                }
#pragma unroll
                for (int nt = 0; nt < 7; ++nt) {
                    int cb = (wn + nt * 8 + g) * 80 + ks * 32 + t * 4;
                    uint32_t bh0 = *(const uint32_t*)(pBH + cb);
                    uint32_t bh1 = *(const uint32_t*)(pBH + cb + 16);
                    uint32_t bl0 = *(const uint32_t*)(pBL + cb);
                    uint32_t bl1 = *(const uint32_t*)(pBL + cb + 16);
#pragma unroll
                    for (int mt = 0; mt < 2; ++mt) {
                        imma32(acch[mt][nt], ah[mt], bh0, bh1);   // hh
                        imma32(accc[mt][nt], ah[mt], bl0, bl1);   // hl
                        imma32(accc[mt][nt], al[mt], bh0, bh1);   // lh
                    }
                }
            }
        }

        if (ch < 12) {
            const int nb = bf ^ 1;
            *(uint4*)(sm + SA_H + nb * 10240 + rA0 * 80 + sg) = pah0;
            *(uint4*)(sm + SA_H + nb * 10240 + rA1 * 80 + sg) = pah1;
            *(uint4*)(sm + SA_L + nb * 10240 + rA0 * 80 + sg) = pal0;
            *(uint4*)(sm + SA_L + nb * 10240 + rA1 * 80 + sg) = pal1;
            *(uint4*)(sm + SB_H + nb * 8960 + rA0 * 80 + sg) = pbh0;
            *(uint4*)(sm + SB_L + nb * 8960 + rA0 * 80 + sg) = pbl0;
            if (hasB1) {
                *(uint4*)(sm + SB_H + nb * 8960 + rB1 * 80 + sg) = pbh1;
                *(uint4*)(sm + SB_L + nb * 8960 + rB1 * 80 + sg) = pbl1;
            }
        }
        __syncthreads();
    }

    // ---- epilogue: descale + bias + store ----
    const float inv128 = 0.0078125f;
#pragma unroll
    for (int mt = 0; mt < 2; ++mt) {
        float sa0 = rsA[m0 + wm + mt * 16 + g];
        float sa1 = rsA[m0 + wm + mt * 16 + g + 8];
#pragma unroll
        for (int nt = 0; nt < 7; ++nt) {
            int col = n0 + wn + nt * 8 + 2 * t;
            float sb0 = rsB[col], sb1 = rsB[col + 1];
            float bv0 = bias[col], bv1 = bias[col + 1];
#pragma unroll
            for (int half = 0; half < 2; ++half) {
                int row = m0 + wm + mt * 16 + g + half * 8;
                float sa = half ? sa1 : sa0;
                float v0 = ((float)acch[mt][nt][half * 2 + 0]
                            + (float)accc[mt][nt][half * 2 + 0] * inv128)
                           * (sa * sb0) + bv0;
                float v1 = ((float)acch[mt][nt][half * 2 + 1]
                            + (float)accc[mt][nt][half * 2 + 1] * inv128)
                           * (sa * sb1) + bv1;
                if (MODE == 0) {
                    int bi = row / 196, n = row % 196;
                    int h0 = col / 196, d0c = col % 196;
                    int h1 = (col + 1) / 196, d1c = (col + 1) % 196;
                    dst[(((size_t)bi * 4 + h0) * 196 + n) * 196 + d0c] = v0;
                    dst[(((size_t)bi * 4 + h1) * 196 + n) * 196 + d1c] = v1;
                } else {
                    dst[(size_t)row * 784 + col]     = v0;
                    dst[(size_t)row * 784 + col + 1] = v1;
                }
            }
        }
    }
}

// ===========================================================================
// Legacy bf16-split attention path (unchanged from R10)
// ===========================================================================
__device__ __forceinline__ void gemm_bk16_bf(const uint32_t (*A)[20],
                                             const uint32_t (*B)[20],
                                             int wm, int wn, int g, int t,
                                             float acc[2][7][4]) {
    uint32_t ah[2][4], al[2][4];
#pragma unroll
    for (int mt = 0; mt < 2; ++mt) {
        const uint32_t* r0 = A[wm + mt * 16 + g];
        const uint32_t* r1 = A[wm + mt * 16 + g + 8];
        ah[mt][0] = r0[t];      ah[mt][1] = r1[t];
        ah[mt][2] = r0[t + 4];  ah[mt][3] = r1[t + 4];
        al[mt][0] = r0[8 + t];     al[mt][1] = r1[8 + t];
        al[mt][2] = r0[12 + t];    al[mt][3] = r1[12 + t];
    }
#pragma unroll
    for (int nt = 0; nt < 7; ++nt) {
        const uint32_t* bc = B[wn + nt * 8 + g];
        uint32_t b0h = bc[t], b1h = bc[t + 4];
        uint32_t b0l = bc[8 + t], b1l = bc[12 + t];
#pragma unroll
        for (int mt = 0; mt < 2; ++mt) {
            mmabf(acc[mt][nt], ah[mt], b0h, b1h);
            mmabf(acc[mt][nt], ah[mt], b0l, b1l);
            mmabf(acc[mt][nt], al[mt], b0h, b1h);
        }
    }
}
__device__ __forceinline__ void st_row(uint32_t (*S)[20], int row, int wq,
                                       float4 v) {
    uint2 h, l;
    split4p(v, h, l);
    *(uint2*)&S[row][wq] = h;
    *(uint2*)&S[row][8 + wq] = l;
}
__device__ __forceinline__ float4 load_row196(const float* P, int row, int k,
                                              bool kval) {
    if (kval) return *(const float4*)&P[(size_t)row * 196 + k];
    return make_float4(0.f, 0.f, 0.f, 0.f);
}
__device__ __forceinline__ void load_trans_bf(const float* P, int j0, int k0,
                                              int tid, float* pv) {
    if (tid < 224) {
        int kp = tid / 28, nq = tid % 28;
        int kr0 = k0 + 2 * kp, kr1 = kr0 + 1;
        int n = j0 + nq * 4;
        if (kr1 < 196 && n + 3 < 196) {
            float4 a = *(const float4*)&P[(size_t)kr0 * 196 + n];
            float4 b = *(const float4*)&P[(size_t)kr1 * 196 + n];
            pv[0] = a.x; pv[1] = a.y; pv[2] = a.z; pv[3] = a.w;
            pv[4] = b.x; pv[5] = b.y; pv[6] = b.z; pv[7] = b.w;
        } else {
#pragma unroll
            for (int j = 0; j < 4; ++j) {
                pv[j]     = (kr0 < 196 && n + j < 196)
                            ? P[(size_t)kr0 * 196 + n + j] : 0.f;
                pv[4 + j] = (kr1 < 196 && n + j < 196)
                            ? P[(size_t)kr1 * 196 + n + j] : 0.f;
            }
        }
    }
}
__device__ __forceinline__ void store_trans_bf(uint32_t (*Bsb)[20], int tid,
                                               const float* pv) {
    if (tid < 224) {
        int kp = tid / 28, nq = tid % 28;
#pragma unroll
        for (int j = 0; j < 4; ++j) {
            uint32_t h, l;
            splitpair(pv[j], pv[4 + j], h, l);
            Bsb[nq * 4 + j][kp] = h;
            Bsb[nq * 4 + j][8 + kp] = l;
        }
    }
}

__global__ __launch_bounds__(256)
void scores_bf() {
    __shared__ uint32_t As[2][128][20];
    __shared__ uint32_t Bs[2][112][20];

    const int batch = blockIdx.z, h = batch & 3;
    const int i0 = blockIdx.y * 128, j0 = blockIdx.x * 112;
    const float* Q  = g_q  + (size_t)batch * 196 * 196;
    const float* Kp = g_k  + (size_t)batch * 196 * 196;
    const float* CP = g_cp + (size_t)h * 196 * 196;

    const int tid = threadIdx.x;
    const int w = tid >> 5, lane = tid & 31;
    const int wm = (w >> 1) * 32, wn = (w & 1) * 56;
    const int g = lane >> 2, t = lane & 3;

    const int rowA0 = tid >> 2, kq = (tid & 3) * 4, wq = (tid & 3) * 2;
    const int rowA1 = (tid + 256) >> 2;
    const bool hasB1 = (tid + 256) < 448;
    const int arA0 = min(i0 + rowA0, 195), arA1 = min(i0 + rowA1, 195);
    const int brA0 = min(j0 + rowA0, 195), brA1 = min(j0 + rowA1, 195);

    float acc[2][7][4];
#pragma unroll
    for (int i = 0; i < 2; i++)
#pragma unroll
        for (int j = 0; j < 7; j++)
#pragma unroll
            for (int c = 0; c < 4; c++) acc[i][j][c] = 0.f;

    {
        st_row(As[0], rowA0, wq, load_row196(Q, arA0, kq, true));
        st_row(As[0], rowA1, wq, load_row196(Q, arA1, kq, true));
        st_row(Bs[0], rowA0, wq, load_row196(Kp, brA0, kq, true));
        if (hasB1) st_row(Bs[0], rowA1, wq, load_row196(Kp, brA1, kq, true));
    }
    __syncthreads();
    for (int it = 0; it < 13; ++it) {
        const int bf = it & 1;
        float4 va0, va1, vb0, vb1;
        if (it < 12) {
            int k0 = (it + 1) * 16;
            bool kv = (k0 + kq) < 196;
            va0 = load_row196(Q, arA0, k0 + kq, kv);
            va1 = load_row196(Q, arA1, k0 + kq, kv);
            vb0 = load_row196(Kp, brA0, k0 + kq, kv);
            if (hasB1) vb1 = load_row196(Kp, brA1, k0 + kq, kv);
        }
        gemm_bk16_bf(As[bf], Bs[bf], wm, wn, g, t, acc);
        if (it < 12) {
            const int nb = bf ^ 1;
            st_row(As[nb], rowA0, wq, va0);
            st_row(As[nb], rowA1, wq, va1);
            st_row(Bs[nb], rowA0, wq, vb0);
            if (hasB1) st_row(Bs[nb], rowA1, wq, vb1);
        }
        __syncthreads();
    }

    const float inv14 = 1.0f / 14.0f;
#pragma unroll
    for (int i = 0; i < 2; i++)
#pragma unroll
        for (int j = 0; j < 7; j++)
#pragma unroll
            for (int c = 0; c < 4; c++) acc[i][j][c] *= inv14;

    __syncthreads();

    {
        float pv[8];
        st_row(As[0], rowA0, wq, load_row196(CP, arA0, kq, true));
        st_row(As[0], rowA1, wq, load_row196(CP, arA1, kq, true));
        load_trans_bf(Q, j0, 0, tid, pv);
        store_trans_bf(Bs[0], tid, pv);
    }
    __syncthreads();
    for (int it = 0; it < 13; ++it) {
        const int bf = it & 1;
        float4 va0, va1;
        float pv[8];
        if (it < 12) {
            int k0 = (it + 1) * 16;
            bool kv = (k0 + kq) < 196;
            va0 = load_row196(CP, arA0, k0 + kq, kv);
            va1 = load_row196(CP, arA1, k0 + kq, kv);
            load_trans_bf(Q, j0, k0, tid, pv);
        }
        gemm_bk16_bf(As[bf], Bs[bf], wm, wn, g, t, acc);
        if (it < 12) {
            const int nb = bf ^ 1;
            st_row(As[nb], rowA0, wq, va0);
            st_row(As[nb], rowA1, wq, va1);
            store_trans_bf(Bs[nb], tid, pv);
        }
        __syncthreads();
    }

    float* S = g_s + (size_t)batch * 196 * 196;
#pragma unroll
    for (int mt = 0; mt < 2; ++mt) {
#pragma unroll
        for (int nt = 0; nt < 7; ++nt) {
            int col = j0 + wn + nt * 8 + 2 * t;
#pragma unroll
            for (int half = 0; half < 2; ++half) {
                int row = i0 + wm + mt * 16 + g + half * 8;
                if (row < 196) {
                    if (col < 196)
                        S[(size_t)row * 196 + col] = acc[mt][nt][half*2+0];
                    if (col + 1 < 196)
                        S[(size_t)row * 196 + col + 1] = acc[mt][nt][half*2+1];
                }
            }
        }
    }
}

__global__ __launch_bounds__(256)
void softmax_kernel() {
    int row  = blockIdx.x * 8 + (threadIdx.x >> 5);
    int lane = threadIdx.x & 31;
    if (row >= BH * NT) return;
    float* S = g_s + (size_t)row * 196;

    float vals[7];
    float mx = -1e30f;
#pragma unroll
    for (int s = 0; s < 7; s++) {
        int j = lane + 32 * s;
        vals[s] = (j < 196) ? S[j] : -1e30f;
        mx = fmaxf(mx, vals[s]);
    }
#pragma unroll
    for (int off = 16; off > 0; off >>= 1)
        mx = fmaxf(mx, __shfl_xor_sync(0xffffffffu, mx, off));

    float sum = 0.f;
#pragma unroll
    for (int s = 0; s < 7; s++) {
        vals[s] = expf(vals[s] - mx);
        sum += vals[s];
    }
#pragma unroll
    for (int off = 16; off > 0; off >>= 1)
        sum += __shfl_xor_sync(0xffffffffu, sum, off);

    float inv = 1.0f / sum;
#pragma unroll
    for (int s = 0; s < 7; s++) {
        int j = lane + 32 * s;
        if (j < 196) S[j] = vals[s] * inv;
    }
}

__global__ __launch_bounds__(256)
void av_bf() {
    __shared__ uint32_t As[2][128][20];
    __shared__ uint32_t Bs[2][112][20];

    const int batch = blockIdx.z;
    const int bi = batch >> 2, h = batch & 3;
    const int i0 = blockIdx.y * 128, d0 = blockIdx.x * 112;
    const float* Sb = g_s + (size_t)batch * 196 * 196;
    const float* V  = g_v + (size_t)batch * 196 * 196;

    const int tid = threadIdx.x;
    const int w = tid >> 5, lane = tid & 31;
    const int wm = (w >> 1) * 32, wn = (w & 1) * 56;
    const int g = lane >> 2, t = lane & 3;

    const int rowA0 = tid >> 2, kq = (tid & 3) * 4, wq = (tid & 3) * 2;
    const int rowA1 = (tid + 256) >> 2;
    const int arA0 = min(i0 + rowA0, 195), arA1 = min(i0 + rowA1, 195);

    float acc[2][7][4];
#pragma unroll
    for (int i = 0; i < 2; i++)
#pragma unroll
        for (int j = 0; j < 7; j++)
#pragma unroll
            for (int c = 0; c < 4; c++) acc[i][j][c] = 0.f;

    {
        float pv[8];
        st_row(As[0], rowA0, wq, load_row196(Sb, arA0, kq, true));
        st_row(As[0], rowA1, wq, load_row196(Sb, arA1, kq, true));
        load_trans_bf(V, d0, 0, tid, pv);
        store_trans_bf(Bs[0], tid, pv);
    }
    __syncthreads();
    for (int it = 0; it < 13; ++it) {
        const int bf = it & 1;
        float4 va0, va1;
        float pv[8];
        if (it < 12) {
            int k0 = (it + 1) * 16;
            bool kv = (k0 + kq) < 196;
            va0 = load_row196(Sb, arA0, k0 + kq, kv);
            va1 = load_row196(Sb, arA1, k0 + kq, kv);
            load_trans_bf(V, d0, k0, tid, pv);
        }
        gemm_bk16_bf(As[bf], Bs[bf], wm, wn, g, t, acc);
        if (it < 12) {
            const int nb = bf ^ 1;
            st_row(As[nb], rowA0, wq, va0);
            st_row(As[nb], rowA1, wq, va1);
            store_trans_bf(Bs[nb], tid, pv);
        }
        __syncthreads();
    }

#pragma unroll
    for (int mt = 0; mt < 2; ++mt) {
#pragma unroll
        for (int nt = 0; nt < 7; ++nt) {
            int col = d0 + wn + nt * 8 + 2 * t;
#pragma unroll
            for (int half = 0; half < 2; ++half) {
                int row = i0 + wm + mt * 16 + g + half * 8;
                if (row < 196) {
                    if (col < 196)
                        g_o[((size_t)bi * 196 + row) * 784 + h * 196 + col]
                            = acc[mt][nt][half*2+0];
                    if (col + 1 < 196)
                        g_o[((size_t)bi * 196 + row) * 784 + h * 196 + col + 1]
                            = acc[mt][nt][half*2+1];
                }
            }
        }
    }
}

// ---------------------------------------------------------------------------
// kernel_launch
// ---------------------------------------------------------------------------
extern "C" void kernel_launch(void* const* d_in, const int* in_sizes, int n_in,
                              void* d_out, int out_size) {
    const float* x     = (const float*)d_in[0];
    const float* Wq    = (const float*)d_in[1];
    const float* bq    = (const float*)d_in[2];
    const float* Wk    = (const float*)d_in[3];
    const float* bk    = (const float*)d_in[4];
    const float* Wv    = (const float*)d_in[5];
    const float* bv    = (const float*)d_in[6];
    const float* Wo    = (const float*)d_in[7];
    const float* bo    = (const float*)d_in[8];
    const float* rel_h = (const float*)d_in[9];
    const float* rel_w = (const float*)d_in[10];
    float* out = (float*)d_out;

    cudaFuncSetAttribute(proj_i8<0>,
        cudaFuncAttributeMaxDynamicSharedMemorySize, SMEM_I8);
    cudaFuncSetAttribute(proj_i8<1>,
        cudaFuncAttributeMaxDynamicSharedMemorySize, SMEM_I8);

    // 1) RPE table
    {
        int n = HH * NT * DD;
        cp_kernel<<<(n + 255) / 256, 256>>>(rel_h, rel_w);
    }
    // 2) quantize x and the four weight matrices
    quant_rows<<<MM, 256>>>(x, 0);
    quant_rows<<<784, 256>>>(Wq, 1);
    quant_rows<<<784, 256>>>(Wk, 2);
    quant_rows<<<784, 256>>>(Wv, 3);
    quant_rows<<<784, 256>>>(Wo, 4);
    // 3) QKV projections (int8)
    {
        dim3 grid(MM / 128, CC / 112, 3);
        proj_i8<0><<<grid, 256, SMEM_I8>>>(bq, bk, bv, nullptr);
    }
    // 4) scores
    {
        dim3 grid(2, 2, BH);
        scores_bf<<<grid, 256>>>();
    }
    // 5) softmax
    softmax_kernel<<<(BH * NT) / 8, 256>>>();
    // 6) attn @ V
    {
        dim3 grid(2, 2, BH);
        av_bf<<<grid, 256>>>();
    }
    // 7) quantize g_o, then output projection (int8)
    quant_rows<<<MM, 256>>>(nullptr, 5);
    {
        dim3 grid(MM / 128, CC / 112, 1);
        proj_i8<1><<<grid, 256, SMEM_I8>>>(bo, nullptr, nullptr, out);
    }
}

// round 15
// speedup vs baseline: 2.0773x; 2.0773x over previous
#include <cuda_runtime.h>
#include <cstdint>

// Problem constants
#define BB 256
#define NT 196
#define CC 784
#define HH 4
#define DD 196
#define MM (BB*NT)      // 50176
#define BH (BB*HH)      // 1024

// ---------------------------------------------------------------------------
// Scratch (static __device__ — no allocations allowed). All plain fp32.
// ---------------------------------------------------------------------------
__device__ float g_q[(size_t)BH*NT*DD];   // (b,h,n,d)
__device__ float g_k[(size_t)BH*NT*DD];
__device__ float g_v[(size_t)BH*NT*DD];
__device__ float g_s[(size_t)BH*NT*NT];   // attn probs
__device__ float g_o[(size_t)BB*NT*CC];   // (b,n,h*d)
__device__ float g_cp[(size_t)HH*NT*DD];  // cp[h][p][k]

// ---------------------------------------------------------------------------
// bf16 2-term split helpers
// ---------------------------------------------------------------------------
__device__ __forceinline__ void splitpair(float x, float y,
                                          uint32_t& hi, uint32_t& lo) {
    uint32_t h;
    asm("cvt.rn.bf16x2.f32 %0, %1, %2;" : "=r"(h) : "f"(y), "f"(x));
    float hx = __uint_as_float(h << 16);
    float hy = __uint_as_float(h & 0xffff0000u);
    asm("cvt.rn.bf16x2.f32 %0, %1, %2;" : "=r"(lo) : "f"(y - hy), "f"(x - hx));
    hi = h;
}
__device__ __forceinline__ void split4p(float4 v, uint2& hi, uint2& lo) {
    splitpair(v.x, v.y, hi.x, lo.x);
    splitpair(v.z, v.w, hi.y, lo.y);
}
__device__ __forceinline__ void mmabf(float* c, const uint32_t* a,
                                      uint32_t b0, uint32_t b1) {
    asm volatile("mma.sync.aligned.m16n8k16.row.col.f32.bf16.bf16.f32 "
                 "{%0,%1,%2,%3}, {%4,%5,%6,%7}, {%8,%9}, {%0,%1,%2,%3};"
                 : "+f"(c[0]), "+f"(c[1]), "+f"(c[2]), "+f"(c[3])
                 : "r"(a[0]), "r"(a[1]), "r"(a[2]), "r"(a[3]),
                   "r"(b0), "r"(b1));
}

// Smem row layout (uint32 words, stride 20): words 0..7 hi pairs k=0..15,
// 8..15 lo pairs, 16..19 pad.
__device__ __forceinline__ void st_row(uint32_t (*S)[20], int row, int wq,
                                       float4 v) {
    uint2 h, l;
    split4p(v, h, l);
    *(uint2*)&S[row][wq] = h;
    *(uint2*)&S[row][8 + wq] = l;
}
__device__ __forceinline__ float4 load_row196(const float* P, int row, int k,
                                              bool kval) {
    if (kval) return *(const float4*)&P[(size_t)row * 196 + k];
    return make_float4(0.f, 0.f, 0.f, 0.f);
}

// One BK=16 chunk, warp tile 32(M) x 56(N) (7 n8 frags), 3 products.
__device__ __forceinline__ void gemm_bk16_bf(const uint32_t (*A)[20],
                                             const uint32_t (*B)[20],
                                             int wm, int wn, int g, int t,
                                             float acc[2][7][4]) {
    uint32_t ah[2][4], al[2][4];
#pragma unroll
    for (int mt = 0; mt < 2; ++mt) {
        const uint32_t* r0 = A[wm + mt * 16 + g];
        const uint32_t* r1 = A[wm + mt * 16 + g + 8];
        ah[mt][0] = r0[t];      ah[mt][1] = r1[t];
        ah[mt][2] = r0[t + 4];  ah[mt][3] = r1[t + 4];
        al[mt][0] = r0[8 + t];     al[mt][1] = r1[8 + t];
        al[mt][2] = r0[12 + t];    al[mt][3] = r1[12 + t];
    }
#pragma unroll
    for (int nt = 0; nt < 7; ++nt) {
        const uint32_t* bc = B[wn + nt * 8 + g];
        uint32_t b0h = bc[t], b1h = bc[t + 4];
        uint32_t b0l = bc[8 + t], b1l = bc[12 + t];
#pragma unroll
        for (int mt = 0; mt < 2; ++mt) {
            mmabf(acc[mt][nt], ah[mt], b0h, b1h);
            mmabf(acc[mt][nt], ah[mt], b0l, b1l);
            mmabf(acc[mt][nt], al[mt], b0h, b1h);
        }
    }
}
// Wide variant: warp tile 32(M) x 104(N) (13 n8 frags).
__device__ __forceinline__ void gemm_bk16_bf13(const uint32_t (*A)[20],
                                               const uint32_t (*B)[20],
                                               int wm, int wn, int g, int t,
                                               float acc[2][13][4]) {
    uint32_t ah[2][4], al[2][4];
#pragma unroll
    for (int mt = 0; mt < 2; ++mt) {
        const uint32_t* r0 = A[wm + mt * 16 + g];
        const uint32_t* r1 = A[wm + mt * 16 + g + 8];
        ah[mt][0] = r0[t];      ah[mt][1] = r1[t];
        ah[mt][2] = r0[t + 4];  ah[mt][3] = r1[t + 4];
        al[mt][0] = r0[8 + t];     al[mt][1] = r1[8 + t];
        al[mt][2] = r0[12 + t];    al[mt][3] = r1[12 + t];
    }
#pragma unroll
    for (int nt = 0; nt < 13; ++nt) {
        const uint32_t* bc = B[wn + nt * 8 + g];
        uint32_t b0h = bc[t], b1h = bc[t + 4];
        uint32_t b0l = bc[8 + t], b1l = bc[12 + t];
#pragma unroll
        for (int mt = 0; mt < 2; ++mt) {
            mmabf(acc[mt][nt], ah[mt], b0h, b1h);
            mmabf(acc[mt][nt], ah[mt], b0l, b1l);
            mmabf(acc[mt][nt], al[mt], b0h, b1h);
        }
    }
}

// cp[h][p][k] = rel_h[h][k][p/14] + rel_w[h][k][p%14]
__global__ void cp_kernel(const float* __restrict__ rel_h,
                          const float* __restrict__ rel_w) {
    int idx = blockIdx.x * blockDim.x + threadIdx.x;
    if (idx >= HH * NT * DD) return;
    int k = idx % DD;
    int p = (idx / DD) % NT;
    int h = idx / (DD * NT);
    g_cp[idx] = rel_h[(h * DD + k) * 14 + p / 14]
              + rel_w[(h * DD + k) * 14 + p % 14];
}

// ---------------------------------------------------------------------------
// Projection GEMM (bf16x2 split): out = A(M x 784) @ W(784 x 784)^T + bias
// Block 128x112, BK=16, 256 threads (8 warps 4x2), double-buffered, occ>=2.
// ---------------------------------------------------------------------------
template <int MODE>
__global__ __launch_bounds__(256, 2)
void proj_bf(const float* __restrict__ Ain,
             const float* __restrict__ W0, const float* __restrict__ W1,
             const float* __restrict__ W2,
             const float* __restrict__ b0p, const float* __restrict__ b1p,
             const float* __restrict__ b2p, float* __restrict__ outp) {
    __shared__ uint32_t As[2][128][20];
    __shared__ uint32_t Bs[2][112][20];

    const int tid = threadIdx.x;
    const int z = (MODE == 0) ? blockIdx.z : 0;
    const float* A = (MODE == 0) ? Ain : g_o;
    const float* W = (MODE == 0) ? ((z == 0) ? W0 : (z == 1) ? W1 : W2) : W0;
    const float* bias = (MODE == 0) ? ((z == 0) ? b0p : (z == 1) ? b1p : b2p)
                                    : b0p;
    float* dst = (MODE == 0) ? ((z == 0) ? g_q : (z == 1) ? g_k : g_v) : outp;

    const int m0 = blockIdx.x * 128, n0 = blockIdx.y * 112;
    const int w = tid >> 5, lane = tid & 31;
    const int wm = (w >> 1) * 32, wn = (w & 1) * 56;
    const int g = lane >> 2, t = lane & 3;

    const int rowA0 = tid >> 2, kq = (tid & 3) * 4, wq = (tid & 3) * 2;
    const int rowA1 = (tid + 256) >> 2;
    const bool hasB1 = (tid + 256) < 448;

    float acc[2][7][4];
#pragma unroll
    for (int i = 0; i < 2; i++)
#pragma unroll
        for (int j = 0; j < 7; j++)
#pragma unroll
            for (int c = 0; c < 4; c++) acc[i][j][c] = 0.f;

    {
        st_row(As[0], rowA0, wq,
               *(const float4*)&A[(size_t)(m0 + rowA0) * 784 + kq]);
        st_row(As[0], rowA1, wq,
               *(const float4*)&A[(size_t)(m0 + rowA1) * 784 + kq]);
        st_row(Bs[0], rowA0, wq,
               *(const float4*)&W[(size_t)(n0 + rowA0) * 784 + kq]);
        if (hasB1)
            st_row(Bs[0], rowA1, wq,
                   *(const float4*)&W[(size_t)(n0 + rowA1) * 784 + kq]);
    }
    __syncthreads();

    for (int it = 0; it < 49; ++it) {
        const int bf = it & 1;
        float4 va0, va1, vb0, vb1;
        if (it < 48) {
            int k0 = (it + 1) * 16;
            va0 = *(const float4*)&A[(size_t)(m0 + rowA0) * 784 + k0 + kq];
            va1 = *(const float4*)&A[(size_t)(m0 + rowA1) * 784 + k0 + kq];
            vb0 = *(const float4*)&W[(size_t)(n0 + rowA0) * 784 + k0 + kq];
            if (hasB1)
                vb1 = *(const float4*)&W[(size_t)(n0 + rowA1) * 784 + k0 + kq];
        }
        gemm_bk16_bf(As[bf], Bs[bf], wm, wn, g, t, acc);
        if (it < 48) {
            const int nb = bf ^ 1;
            st_row(As[nb], rowA0, wq, va0);
            st_row(As[nb], rowA1, wq, va1);
            st_row(Bs[nb], rowA0, wq, vb0);
            if (hasB1) st_row(Bs[nb], rowA1, wq, vb1);
        }
        __syncthreads();
    }

#pragma unroll
    for (int mt = 0; mt < 2; ++mt) {
#pragma unroll
        for (int nt = 0; nt < 7; ++nt) {
            int col = n0 + wn + nt * 8 + 2 * t;
            float bv0 = bias[col], bv1 = bias[col + 1];
#pragma unroll
            for (int half = 0; half < 2; ++half) {
                int row = m0 + wm + mt * 16 + g + half * 8;
                float v0 = acc[mt][nt][half * 2 + 0] + bv0;
                float v1 = acc[mt][nt][half * 2 + 1] + bv1;
                if (MODE == 0) {
                    int bi = row / 196, n = row % 196;
                    int h0 = col / 196, d0c = col % 196;
                    int h1 = (col + 1) / 196, d1c = (col + 1) % 196;
                    dst[(((size_t)bi * 4 + h0) * 196 + n) * 196 + d0c] = v0;
                    dst[(((size_t)bi * 4 + h1) * 196 + n) * 196 + d1c] = v1;
                } else {
                    dst[(size_t)row * 784 + col]     = v0;
                    dst[(size_t)row * 784 + col + 1] = v1;
                }
            }
        }
    }
}

// ---------------------------------------------------------------------------
// Fused scores + softmax: per (b,h), block = 128 rows x 208 cols (full row).
// S = softmax(Q K^T / 14 + Cp @ Q). grid (2, 1024), 256 threads.
// Dynamic smem: As[2][128][20] (5120 w) + Bs[2][208][20] (8320 w) = 53760 B.
// Epilogue stages 64 rows at a time into the (reused) smem for row softmax.
// ---------------------------------------------------------------------------
#define SC_SMEM_WORDS 13440
#define SC_SMEM_BYTES (SC_SMEM_WORDS * 4)

__global__ __launch_bounds__(256)
void scores_fused() {
    extern __shared__ uint32_t sm[];
    uint32_t (*As)[20] = (uint32_t (*)[20])(sm);            // [2*128][20]
    uint32_t (*Bs)[20] = (uint32_t (*)[20])(sm + 5120);     // [2*208][20]

    const int batch = blockIdx.y, h = batch & 3;
    const int i0 = blockIdx.x * 128;
    const float* Q  = g_q  + (size_t)batch * 196 * 196;
    const float* Kp = g_k  + (size_t)batch * 196 * 196;
    const float* CP = g_cp + (size_t)h * 196 * 196;

    const int tid = threadIdx.x;
    const int w = tid >> 5, lane = tid & 31;
    const int wm = (w >> 1) * 32, wn = (w & 1) * 104;
    const int g = lane >> 2, t = lane & 3;

    const int rowA0 = tid >> 2, kq = (tid & 3) * 4, wq = (tid & 3) * 2;
    const int rowA1 = (tid + 256) >> 2;
    const int arA0 = min(i0 + rowA0, 195), arA1 = min(i0 + rowA1, 195);

    float acc[2][13][4];
#pragma unroll
    for (int i = 0; i < 2; i++)
#pragma unroll
        for (int j = 0; j < 13; j++)
#pragma unroll
            for (int c = 0; c < 4; c++) acc[i][j][c] = 0.f;

    // ================= pass 1: Q K^T =================
    {
        st_row(&As[0], rowA0, wq, load_row196(Q, arA0, kq, true));
        st_row(&As[0], rowA1, wq, load_row196(Q, arA1, kq, true));
#pragma unroll
        for (int s = 0; s < 4; ++s) {
            int u = tid + s * 256;
            if (u < 832) {
                int row = u >> 2, qk = (u & 3) * 4;
                st_row(&Bs[0], row, (u & 3) * 2,
                       load_row196(Kp, min(row, 195), qk, true));
            }
        }
    }
    __syncthreads();
    for (int it = 0; it < 13; ++it) {
        const int bf = it & 1;
        float4 va0, va1, pb[4];
        if (it < 12) {
            int k0 = (it + 1) * 16;
            bool kv = (k0 + kq) < 196;
            va0 = load_row196(Q, arA0, k0 + kq, kv);
            va1 = load_row196(Q, arA1, k0 + kq, kv);
#pragma unroll
            for (int s = 0; s < 4; ++s) {
                int u = tid + s * 256;
                if (u < 832) {
                    int row = u >> 2, qk = (u & 3) * 4;
                    pb[s] = load_row196(Kp, min(row, 195), k0 + qk,
                                        (k0 + qk) < 196);
                }
            }
        }
        gemm_bk16_bf13(&As[bf * 128], &Bs[bf * 208], wm, wn, g, t, acc);
        if (it < 12) {
            const int nb = bf ^ 1;
            st_row(&As[nb * 128], rowA0, wq, va0);
            st_row(&As[nb * 128], rowA1, wq, va1);
#pragma unroll
            for (int s = 0; s < 4; ++s) {
                int u = tid + s * 256;
                if (u < 832)
                    st_row(&Bs[nb * 208], u >> 2, (u & 3) * 2, pb[s]);
            }
        }
        __syncthreads();
    }

    const float inv14 = 1.0f / 14.0f;
#pragma unroll
    for (int i = 0; i < 2; i++)
#pragma unroll
        for (int j = 0; j < 13; j++)
#pragma unroll
            for (int c = 0; c < 4; c++) acc[i][j][c] *= inv14;

    __syncthreads();

    // ================= pass 2: Cp @ Q (B = Q^T gather) =================
    {
        st_row(&As[0], rowA0, wq, load_row196(CP, arA0, kq, true));
        st_row(&As[0], rowA1, wq, load_row196(CP, arA1, kq, true));
#pragma unroll
        for (int s = 0; s < 2; ++s) {
            int u = tid + s * 256;
            if (u < 416) {
                int kp = u / 52, nq = u % 52;
                int kr0 = 2 * kp, kr1 = kr0 + 1;
#pragma unroll
                for (int j = 0; j < 4; ++j) {
                    int n = nq * 4 + j;
                    float a = (n < 196) ? Q[(size_t)kr0 * 196 + n] : 0.f;
                    float b = (n < 196) ? Q[(size_t)kr1 * 196 + n] : 0.f;
                    uint32_t hh, ll;
                    splitpair(a, b, hh, ll);
                    Bs[nq * 4 + j][kp] = hh;
                    Bs[nq * 4 + j][8 + kp] = ll;
                }
            }
        }
    }
    __syncthreads();
    for (int it = 0; it < 13; ++it) {
        const int bf = it & 1;
        float4 va0, va1;
        float pv[2][8];
        if (it < 12) {
            int k0 = (it + 1) * 16;
            bool kv = (k0 + kq) < 196;
            va0 = load_row196(CP, arA0, k0 + kq, kv);
            va1 = load_row196(CP, arA1, k0 + kq, kv);
#pragma unroll
            for (int s = 0; s < 2; ++s) {
                int u = tid + s * 256;
                if (u < 416) {
                    int kp = u / 52, nq = u % 52;
                    int kr0 = k0 + 2 * kp, kr1 = kr0 + 1;
#pragma unroll
                    for (int j = 0; j < 4; ++j) {
                        int n = nq * 4 + j;
                        pv[s][j] = (kr0 < 196 && n < 196)
                                   ? Q[(size_t)kr0 * 196 + n] : 0.f;
                        pv[s][4 + j] = (kr1 < 196 && n < 196)
                                       ? Q[(size_t)kr1 * 196 + n] : 0.f;
                    }
                }
            }
        }
        gemm_bk16_bf13(&As[bf * 128], &Bs[bf * 208], wm, wn, g, t, acc);
        if (it < 12) {
            const int nb = bf ^ 1;
            st_row(&As[nb * 128], rowA0, wq, va0);
            st_row(&As[nb * 128], rowA1, wq, va1);
#pragma unroll
            for (int s = 0; s < 2; ++s) {
                int u = tid + s * 256;
                if (u < 416) {
                    int kp = u / 52, nq = u % 52;
#pragma unroll
                    for (int j = 0; j < 4; ++j) {
                        uint32_t hh, ll;
                        splitpair(pv[s][j], pv[s][4 + j], hh, ll);
                        Bs[nb * 208 + nq * 4 + j][kp] = hh;
                        Bs[nb * 208 + nq * 4 + j][8 + kp] = ll;
                    }
                }
            }
        }
        __syncthreads();
    }

    // ================= fused softmax epilogue =================
    float* stage = (float*)sm;     // [64][209]
    float* S = g_s + (size_t)batch * 196 * 196;
#pragma unroll
    for (int wv = 0; wv < 2; ++wv) {
        // scatter acc rows of this wave into stage
#pragma unroll
        for (int mt = 0; mt < 2; ++mt) {
#pragma unroll
            for (int half = 0; half < 2; ++half) {
                int r = wm + mt * 16 + g + half * 8;
                if ((r >> 6) == wv) {
                    int rl = r & 63;
#pragma unroll
                    for (int nt = 0; nt < 13; ++nt) {
                        int col = wn + nt * 8 + 2 * t;
                        stage[rl * 209 + col]     = acc[mt][nt][half*2+0];
                        stage[rl * 209 + col + 1] = acc[mt][nt][half*2+1];
                    }
                }
            }
        }
        __syncthreads();
        // one warp per row (8 rows per warp), softmax over 196 cols
        for (int ii = 0; ii < 8; ++ii) {
            int rl = w * 8 + ii;
            int gr = i0 + wv * 64 + rl;
            if (gr < 196) {
                float vals[7];
                float mx = -1e30f;
#pragma unroll
                for (int s = 0; s < 7; ++s) {
                    int c = lane + 32 * s;
                    vals[s] = (c < 196) ? stage[rl * 209 + c] : -1e30f;
                    mx = fmaxf(mx, vals[s]);
                }
#pragma unroll
                for (int o = 16; o; o >>= 1)
                    mx = fmaxf(mx, __shfl_xor_sync(0xffffffffu, mx, o));
                float sum = 0.f;
#pragma unroll
                for (int s = 0; s < 7; ++s) {
                    vals[s] = expf(vals[s] - mx);
                    sum += vals[s];
                }
#pragma unroll
                for (int o = 16; o; o >>= 1)
                    sum += __shfl_xor_sync(0xffffffffu, sum, o);
                float inv = 1.0f / sum;
#pragma unroll
                for (int s = 0; s < 7; ++s) {
                    int c = lane + 32 * s;
                    if (c < 196) S[(size_t)gr * 196 + c] = vals[s] * inv;
                }
            }
        }
        __syncthreads();
    }
}

// ---------------------------------------------------------------------------
// attn @ V (bf16x2 split), head-merged fp32 store into g_o.
// ---------------------------------------------------------------------------
__device__ __forceinline__ void load_trans_bf(const float* P, int j0, int k0,
                                              int tid, float* pv) {
    if (tid < 224) {
        int kp = tid / 28, nq = tid % 28;
        int kr0 = k0 + 2 * kp, kr1 = kr0 + 1;
        int n = j0 + nq * 4;
        if (kr1 < 196 && n + 3 < 196) {
            float4 a = *(const float4*)&P[(size_t)kr0 * 196 + n];
            float4 b = *(const float4*)&P[(size_t)kr1 * 196 + n];
            pv[0] = a.x; pv[1] = a.y; pv[2] = a.z; pv[3] = a.w;
            pv[4] = b.x; pv[5] = b.y; pv[6] = b.z; pv[7] = b.w;
        } else {
#pragma unroll
            for (int j = 0; j < 4; ++j) {
                pv[j]     = (kr0 < 196 && n + j < 196)
                            ? P[(size_t)kr0 * 196 + n + j] : 0.f;
                pv[4 + j] = (kr1 < 196 && n + j < 196)
                            ? P[(size_t)kr1 * 196 + n + j] : 0.f;
            }
        }
    }
}
__device__ __forceinline__ void store_trans_bf(uint32_t (*Bsb)[20], int tid,
                                               const float* pv) {
    if (tid < 224) {
        int kp = tid / 28, nq = tid % 28;
#pragma unroll
        for (int j = 0; j < 4; ++j) {
            uint32_t h, l;
            splitpair(pv[j], pv[4 + j], h, l);
            Bsb[nq * 4 + j][kp] = h;
            Bsb[nq * 4 + j][8 + kp] = l;
        }
    }
}

__global__ __launch_bounds__(256, 2)
void av_bf() {
    __shared__ uint32_t As[2][128][20];
    __shared__ uint32_t Bs[2][112][20];

    const int batch = blockIdx.z;
    const int bi = batch >> 2, h = batch & 3;
    const int i0 = blockIdx.y * 128, d0 = blockIdx.x * 112;
    const float* Sb = g_s + (size_t)batch * 196 * 196;
    const float* V  = g_v + (size_t)batch * 196 * 196;

    const int tid = threadIdx.x;
    const int w = tid >> 5, lane = tid & 31;
    const int wm = (w >> 1) * 32, wn = (w & 1) * 56;
    const int g = lane >> 2, t = lane & 3;

    const int rowA0 = tid >> 2, kq = (tid & 3) * 4, wq = (tid & 3) * 2;
    const int rowA1 = (tid + 256) >> 2;
    const int arA0 = min(i0 + rowA0, 195), arA1 = min(i0 + rowA1, 195);

    float acc[2][7][4];
#pragma unroll
    for (int i = 0; i < 2; i++)
#pragma unroll
        for (int j = 0; j < 7; j++)
#pragma unroll
            for (int c = 0; c < 4; c++) acc[i][j][c] = 0.f;

    {
        float pv[8];
        st_row(As[0], rowA0, wq, load_row196(Sb, arA0, kq, true));
        st_row(As[0], rowA1, wq, load_row196(Sb, arA1, kq, true));
        load_trans_bf(V, d0, 0, tid, pv);
        store_trans_bf(Bs[0], tid, pv);
    }
    __syncthreads();
    for (int it = 0; it < 13; ++it) {
        const int bf = it & 1;
        float4 va0, va1;
        float pv[8];
        if (it < 12) {
            int k0 = (it + 1) * 16;
            bool kv = (k0 + kq) < 196;
            va0 = load_row196(Sb, arA0, k0 + kq, kv);
            va1 = load_row196(Sb, arA1, k0 + kq, kv);
            load_trans_bf(V, d0, k0, tid, pv);
        }
        gemm_bk16_bf(As[bf], Bs[bf], wm, wn, g, t, acc);
        if (it < 12) {
            const int nb = bf ^ 1;
            st_row(As[nb], rowA0, wq, va0);
            st_row(As[nb], rowA1, wq, va1);
            store_trans_bf(Bs[nb], tid, pv);
        }
        __syncthreads();
    }

#pragma unroll
    for (int mt = 0; mt < 2; ++mt) {
#pragma unroll
        for (int nt = 0; nt < 7; ++nt) {
            int col = d0 + wn + nt * 8 + 2 * t;
#pragma unroll
            for (int half = 0; half < 2; ++half) {
                int row = i0 + wm + mt * 16 + g + half * 8;
                if (row < 196) {
                    if (col < 196)
                        g_o[((size_t)bi * 196 + row) * 784 + h * 196 + col]
                            = acc[mt][nt][half*2+0];
                    if (col + 1 < 196)
                        g_o[((size_t)bi * 196 + row) * 784 + h * 196 + col + 1]
                            = acc[mt][nt][half*2+1];
                }
            }
        }
    }
}

// ---------------------------------------------------------------------------
// kernel_launch
// ---------------------------------------------------------------------------
extern "C" void kernel_launch(void* const* d_in, const int* in_sizes, int n_in,
                              void* d_out, int out_size) {
    const float* x     = (const float*)d_in[0];
    const float* Wq    = (const float*)d_in[1];
    const float* bq    = (const float*)d_in[2];
    const float* Wk    = (const float*)d_in[3];
    const float* bk    = (const float*)d_in[4];
    const float* Wv    = (const float*)d_in[5];
    const float* bv    = (const float*)d_in[6];
    const float* Wo    = (const float*)d_in[7];
    const float* bo    = (const float*)d_in[8];
    const float* rel_h = (const float*)d_in[9];
    const float* rel_w = (const float*)d_in[10];
    float* out = (float*)d_out;

    cudaFuncSetAttribute(scores_fused,
        cudaFuncAttributeMaxDynamicSharedMemorySize, SC_SMEM_BYTES);

    // 1) RPE table
    {
        int n = HH * NT * DD;
        cp_kernel<<<(n + 255) / 256, 256>>>(rel_h, rel_w);
    }
    // 2) QKV projections
    {
        dim3 grid(MM / 128, CC / 112, 3);
        proj_bf<0><<<grid, 256>>>(x, Wq, Wk, Wv, bq, bk, bv, nullptr);
    }
    // 3) scores + softmax (fused)
    {
        dim3 grid(2, BH);
        scores_fused<<<grid, 256, SC_SMEM_BYTES>>>();
    }
    // 4) attn @ V
    {
        dim3 grid(2, 2, BH);
        av_bf<<<grid, 256>>>();
    }
    // 5) output projection
    {
        dim3 grid(MM / 128, CC / 112, 1);
        proj_bf<1><<<grid, 256>>>(nullptr, Wo, nullptr, nullptr, bo, nullptr,
                                  nullptr, out);
    }
}